// round 15
// baseline (speedup 1.0000x reference)
#include <cuda_runtime.h>
#include <cuda_fp16.h>
#include <cstddef>
#include <cstdint>

#define N_NODES 65536
#define KTAPS   27
#define COUT    128
#define BN_EPS  1e-3f

// ==================== helpers ====================
__device__ __forceinline__ uint32_t smem_to_u32(const void* p) {
    uint32_t a;
    asm("{ .reg .u64 t; cvta.to.shared.u64 t, %1; cvt.u32.u64 %0, t; }" : "=r"(a) : "l"(p));
    return a;
}
__device__ __forceinline__ void ldsm_x4(uint32_t& r0, uint32_t& r1, uint32_t& r2, uint32_t& r3,
                                        uint32_t addr) {
    asm volatile("ldmatrix.sync.aligned.m8n8.x4.shared.b16 {%0,%1,%2,%3}, [%4];"
                 : "=r"(r0), "=r"(r1), "=r"(r2), "=r"(r3) : "r"(addr));
}
__device__ __forceinline__ void mma_f16(float* c, const uint32_t* a, const uint32_t* b) {
    asm volatile(
        "mma.sync.aligned.m16n8k16.row.col.f32.f16.f16.f32 "
        "{%0,%1,%2,%3}, {%4,%5,%6,%7}, {%8,%9}, {%0,%1,%2,%3};"
        : "+f"(c[0]), "+f"(c[1]), "+f"(c[2]), "+f"(c[3])
        : "r"(a[0]), "r"(a[1]), "r"(a[2]), "r"(a[3]), "r"(b[0]), "r"(b[1]));
}
__device__ __forceinline__ void cp16(uint32_t s, const void* g) {
    asm volatile("{ .reg .u64 gg; cvta.to.global.u64 gg, %1;"
                 "  cp.async.cg.shared.global [%0], [gg], 16; }"
                 :: "r"(s), "l"(g) : "memory");
}
#define CP_COMMIT() asm volatile("cp.async.commit_group;" ::: "memory")
#define CP_WAIT1()  asm volatile("cp.async.wait_group 1;" ::: "memory")
#define CP_WAIT0()  asm volatile("cp.async.wait_group 0;" ::: "memory")

// ==================== scratch (static device memory; no allocs) ====================
__device__ __half g_x16[(size_t)N_NODES * 64];            // x fp16, node-major
__device__ __half g_wa16[(size_t)KTAPS * 128 * 64];       // [k][o][c64]
__device__ __half g_wb16[(size_t)KTAPS * 2 * 128 * 64];   // [k][ch][o][c64]
__device__ __half g_ws16[(size_t)128 * 64];
__device__ float  g_ya[(size_t)N_NODES * COUT];           // conv_a out fp32, node-major
__device__ __half g_ya16[(size_t)N_NODES * COUT];         // relu(BN_a(ya)) fp16
__device__ float  g_yb[(size_t)COUT * N_NODES];           // conv_b out, ch-major
__device__ float  g_sk[(size_t)COUT * N_NODES];           // skip out,  ch-major
__device__ float  g_stat[6 * COUT];                       // a:[0,2C) b:[2C,4C) s:[4C,6C)
__device__ float  g_scale_a[COUT];
__device__ float  g_bias_a[COUT];
__device__ float  g_coef[4 * COUT];

// ==================== tiny: zero stat accumulators ====================
__global__ void zero_stat_kernel(float* acc) {
    acc[blockIdx.x * 256 + threadIdx.x] = 0.f;
}

// ==================== x transpose + fp16 convert ====================
__global__ void xconv_kernel(const float* __restrict__ x,
                             __half* __restrict__ x16) {
    __shared__ float tile[32][33];
    int nb = blockIdx.x * 32, cb = blockIdx.y * 32;
    int tx = threadIdx.x, ty = threadIdx.y;
#pragma unroll
    for (int i = 0; i < 4; i++)
        tile[ty + i * 8][tx] = x[(size_t)(cb + ty + i * 8) * N_NODES + nb + tx];
    __syncthreads();
#pragma unroll
    for (int i = 0; i < 4; i++)
        x16[(size_t)(nb + ty + i * 8) * 64 + cb + tx] =
            __float2half_rn(tile[tx][ty + i * 8]);
}

// ==================== weight convert: w[o][c][k] -> fp16 [k][ch64][o][c64] ====================
__global__ void wconv_kernel(const float* __restrict__ w,
                             __half* __restrict__ w16,
                             int C, int K) {
    int i = blockIdx.x * 256 + threadIdx.x;
    int total = 128 * C * K;
    if (i >= total) return;
    int CH = C / 64;
    int cl = i & 63;
    int o  = (i >> 6) & 127;
    int kc = i >> 13;
    int ch = kc % CH;
    int k  = kc / CH;
    int c  = ch * 64 + cl;
    w16[i] = __float2half_rn(w[((size_t)o * C + c) * K + k]);
}

// ==================== gathered conv GEMM on HMMA (fp16, 1-pass, occ 2) ====================
// D[node, out] = sum_{k,c} act[node,k,c] * w[out,k,c]
// 8 warps, warp tile 64x32, CC=64 chunk, 3-stage cp.async ring, 2 CTAs/SM.
// Epilogue also accumulates per-channel BN partial sums (sum, sumsq) via atomics.
template<int CIN, int KT, bool GATHER, bool CHMAJOR>
__global__ __launch_bounds__(256, 2)
void tconv_kernel(const __half* __restrict__ src,
                  const __half* __restrict__ w16,
                  const int* __restrict__ neigh,
                  float* __restrict__ out,
                  float* __restrict__ statp) {
    constexpr int CH = CIN / 64;
    constexpr int STEPS = KT * CH;
    constexpr int RS = 144;                       // 128 B row + 16 pad
    constexpr uint32_t AH = 0, WH = 18432, BUF = 36864;
    extern __shared__ __align__(16) char smem[];
    const uint32_t sb = smem_to_u32(smem);

    const int t = threadIdx.x;
    const int lane = t & 31, wid = t >> 5;
    const int n_base = blockIdx.x * 128;
    const int warp_m = (wid & 1) * 64;
    const int warp_n = (wid >> 1) * 32;
    const uint32_t aoff_lane = (uint32_t)(warp_m + (lane & 15)) * RS + ((lane & 16) ? 16u : 0u);
    const uint32_t boff_lane = (uint32_t)(warp_n + (lane & 7) + ((lane & 16) ? 8 : 0)) * RS
                               + ((lane & 8) ? 16u : 0u);

    const int row = t >> 1, part = t & 1;

    float acc[4][4][4];
#pragma unroll
    for (int mi = 0; mi < 4; mi++)
#pragma unroll
        for (int ni = 0; ni < 4; ni++)
#pragma unroll
            for (int e = 0; e < 4; e++) acc[mi][ni][e] = 0.f;

    auto j_of = [&](int s) -> int {
        return GATHER ? neigh[(size_t)(n_base + row) * KT + (s / CH)] : (n_base + row);
    };

    auto issue = [&](int s, int j) {
        const uint32_t stg = sb + (uint32_t)(s % 3) * BUF;
        const int k = s / CH, ch = s % CH;
        const __half* ap = src + (size_t)j * CIN + ch * 64 + part * 32;
        const uint32_t ab = stg + AH + (uint32_t)row * RS + part * 64;
#pragma unroll
        for (int i = 0; i < 4; i++)
            cp16(ab + i * 16, ap + i * 8);
        const __half* wp = w16 + ((size_t)(k * CH + ch) << 13) + row * 64 + part * 32;
        const uint32_t wb = stg + WH + (uint32_t)row * RS + part * 64;
#pragma unroll
        for (int i = 0; i < 4; i++)
            cp16(wb + i * 16, wp + i * 8);
        CP_COMMIT();
    };

    int jn = j_of(0);
    issue(0, jn);
    if (STEPS > 1) jn = j_of(1);

    for (int s = 0; s < STEPS; ++s) {
        if (s + 1 < STEPS) {
            issue(s + 1, jn);                    // writes buf (s+1)%3 — safe at depth 3
            if (s + 2 < STEPS) jn = j_of(s + 2);
            CP_WAIT1();
        } else {
            CP_WAIT0();
        }
        __syncthreads();

        const uint32_t sbuf = sb + (uint32_t)(s % 3) * BUF;

#pragma unroll
        for (int k16 = 0; k16 < 4; ++k16) {
            const uint32_t kb = (uint32_t)k16 * 32;
            const uint32_t a_h = sbuf + AH + aoff_lane + kb;
            const uint32_t b_h = sbuf + WH + boff_lane + kb;

            uint32_t ah[4][4], bh[4][2];
#pragma unroll
            for (int mi = 0; mi < 4; mi++)
                ldsm_x4(ah[mi][0], ah[mi][1], ah[mi][2], ah[mi][3], a_h + mi * (16 * RS));
#pragma unroll
            for (int nt = 0; nt < 2; nt++) {
                uint32_t r0, r1, r2, r3;
                ldsm_x4(r0, r1, r2, r3, b_h + nt * (16 * RS));
                bh[2 * nt][0] = r0; bh[2 * nt][1] = r1;
                bh[2 * nt + 1][0] = r2; bh[2 * nt + 1][1] = r3;
            }
#pragma unroll
            for (int mi = 0; mi < 4; mi++)
#pragma unroll
                for (int ni = 0; ni < 4; ni++)
                    mma_f16(acc[mi][ni], ah[mi], bh[ni]);
        }
    }

    // ---- epilogue: store + fused per-channel BN partial stats ----
#pragma unroll
    for (int mi = 0; mi < 4; mi++)
#pragma unroll
        for (int ni = 0; ni < 4; ni++) {
            int r = n_base + warp_m + mi * 16 + (lane >> 2);
            int c = warp_n + ni * 8 + (lane & 3) * 2;
            if (CHMAJOR) {
                out[(size_t)c * N_NODES + r]           = acc[mi][ni][0];
                out[(size_t)(c + 1) * N_NODES + r]     = acc[mi][ni][1];
                out[(size_t)c * N_NODES + r + 8]       = acc[mi][ni][2];
                out[(size_t)(c + 1) * N_NODES + r + 8] = acc[mi][ni][3];
            } else {
                *(float2*)&out[(size_t)r * COUT + c] =
                    make_float2(acc[mi][ni][0], acc[mi][ni][1]);
                *(float2*)&out[(size_t)(r + 8) * COUT + c] =
                    make_float2(acc[mi][ni][2], acc[mi][ni][3]);
            }
        }

    {
        // per-thread channel partials: p = ni*2 + h -> channel warp_n + ni*8 + (lane&3)*2 + h
        float sloc[8], qloc[8];
#pragma unroll
        for (int ni = 0; ni < 4; ni++)
#pragma unroll
            for (int h = 0; h < 2; h++) {
                float s = 0.f, q = 0.f;
#pragma unroll
                for (int mi = 0; mi < 4; mi++) {
                    float v0 = acc[mi][ni][h];
                    float v1 = acc[mi][ni][h + 2];
                    s += v0 + v1;
                    q += v0 * v0 + v1 * v1;
                }
                sloc[ni * 2 + h] = s;
                qloc[ni * 2 + h] = q;
            }
        // reduce over the 8 lanes sharing (lane & 3)
#pragma unroll
        for (int off = 4; off < 32; off <<= 1)
#pragma unroll
            for (int p = 0; p < 8; p++) {
                sloc[p] += __shfl_xor_sync(0xffffffffu, sloc[p], off);
                qloc[p] += __shfl_xor_sync(0xffffffffu, qloc[p], off);
            }
        if ((lane >> 2) == 0) {
#pragma unroll
            for (int p = 0; p < 8; p++) {
                int c = warp_n + (p >> 1) * 8 + (lane & 3) * 2 + (p & 1);
                atomicAdd(&statp[c], sloc[p]);
                atomicAdd(&statp[COUT + c], qloc[p]);
            }
        }
    }
}

// ==================== BN_a finalize ====================
__global__ void stats_fin_kernel(const float* __restrict__ acc,
                                 const float* __restrict__ gamma,
                                 const float* __restrict__ beta,
                                 float* __restrict__ scale,
                                 float* __restrict__ bias) {
    int c = threadIdx.x;
    float mean = acc[c] / N_NODES;
    float var  = acc[COUT + c] / N_NODES - mean * mean;
    float kk   = gamma[c] * rsqrtf(var + BN_EPS);
    scale[c] = kk;
    bias[c]  = beta[c] - kk * mean;
}

// ==================== BN_b + BN_s finalize (from fused accumulators) ====================
__global__ void stats_fin2_kernel(const float* __restrict__ acc,  // [2C,6C) region base
                                  const float* __restrict__ gb,
                                  const float* __restrict__ bb,
                                  const float* __restrict__ gs,
                                  const float* __restrict__ bs,
                                  float* __restrict__ coef) {
    int c = threadIdx.x;
    float m1 = acc[c] / N_NODES;
    float v1 = acc[COUT + c] / N_NODES - m1 * m1;
    float k1 = gb[c] * rsqrtf(v1 + BN_EPS);
    coef[c]            = k1;
    coef[COUT + c]     = bb[c] - k1 * m1;
    float m2 = acc[2 * COUT + c] / N_NODES;
    float v2 = acc[3 * COUT + c] / N_NODES - m2 * m2;
    float k2 = gs[c] * rsqrtf(v2 + BN_EPS);
    coef[2 * COUT + c] = k2;
    coef[3 * COUT + c] = bs[c] - k2 * m2;
}

// ==================== yaconv: relu(BN_a(ya)) -> fp16 ====================
__global__ void yaconv_kernel(const float* __restrict__ ya,
                              const float* __restrict__ scale,
                              const float* __restrict__ bias,
                              __half* __restrict__ y16) {
    int i = blockIdx.x * 256 + threadIdx.x;      // quad index
    int c0 = (i & 31) * 4;
    float4 v  = ((const float4*)ya)[i];
    float4 sc = *(const float4*)(scale + c0);
    float4 bi = *(const float4*)(bias + c0);
    float a0 = fmaxf(fmaf(v.x, sc.x, bi.x), 0.f);
    float a1 = fmaxf(fmaf(v.y, sc.y, bi.y), 0.f);
    float a2 = fmaxf(fmaf(v.z, sc.z, bi.z), 0.f);
    float a3 = fmaxf(fmaf(v.w, sc.w, bi.w), 0.f);
    ((__half2*)y16)[i * 2]     = __floats2half2_rn(a0, a1);
    ((__half2*)y16)[i * 2 + 1] = __floats2half2_rn(a2, a3);
}

// ==================== final: out = relu(BN_b(yb) + BN_s(sk)) ====================
__global__ void final_ew_kernel(const float* __restrict__ yb,
                                const float* __restrict__ sk,
                                const float* __restrict__ coef,
                                float* __restrict__ out) {
    int i = blockIdx.x * 256 + threadIdx.x;
    int o = i >> 14;
    float sb = coef[o],            bb = coef[COUT + o];
    float ss = coef[2 * COUT + o], bs = coef[3 * COUT + o];
    float4 a = ((const float4*)yb)[i];
    float4 b = ((const float4*)sk)[i];
    float4 r;
    r.x = fmaxf(fmaf(sb, a.x, bb) + fmaf(ss, b.x, bs), 0.f);
    r.y = fmaxf(fmaf(sb, a.y, bb) + fmaf(ss, b.y, bs), 0.f);
    r.z = fmaxf(fmaf(sb, a.z, bb) + fmaf(ss, b.z, bs), 0.f);
    r.w = fmaxf(fmaf(sb, a.w, bb) + fmaf(ss, b.w, bs), 0.f);
    ((float4*)out)[i] = r;
}

// ==================== host ====================
static constexpr int TCONV_SMEM = 3 * 36864;   // 110592 B -> 2 CTAs/SM

extern "C" void kernel_launch(void* const* d_in, const int* in_sizes, int n_in,
                              void* d_out, int out_size) {
    const float* data    = (const float*)d_in[0];
    const int*   neigh   = (const int*)  d_in[1];
    const float* w_a     = (const float*)d_in[2];
    const float* w_b     = (const float*)d_in[3];
    const float* w_skip  = (const float*)d_in[4];
    const float* gamma_a = (const float*)d_in[5];
    const float* beta_a  = (const float*)d_in[6];
    const float* gamma_b = (const float*)d_in[7];
    const float* beta_b  = (const float*)d_in[8];
    const float* gamma_s = (const float*)d_in[9];
    const float* beta_s  = (const float*)d_in[10];
    float* out = (float*)d_out;

    __half *x16, *wa16, *wb16, *ws16, *ya16;
    float *ya, *yb, *sk, *stat, *sca, *bia, *coef;
    cudaGetSymbolAddress((void**)&x16,  g_x16);
    cudaGetSymbolAddress((void**)&wa16, g_wa16);
    cudaGetSymbolAddress((void**)&wb16, g_wb16);
    cudaGetSymbolAddress((void**)&ws16, g_ws16);
    cudaGetSymbolAddress((void**)&ya,   g_ya);
    cudaGetSymbolAddress((void**)&ya16, g_ya16);
    cudaGetSymbolAddress((void**)&yb,   g_yb);
    cudaGetSymbolAddress((void**)&sk,   g_sk);
    cudaGetSymbolAddress((void**)&stat, g_stat);
    cudaGetSymbolAddress((void**)&sca,  g_scale_a);
    cudaGetSymbolAddress((void**)&bia,  g_bias_a);
    cudaGetSymbolAddress((void**)&coef, g_coef);

    auto* ka = tconv_kernel<64, KTAPS, true, false>;
    auto* kb = tconv_kernel<128, KTAPS, true, true>;
    auto* ks = tconv_kernel<64, 1, false, true>;
    cudaFuncSetAttribute(ka, cudaFuncAttributeMaxDynamicSharedMemorySize, TCONV_SMEM);
    cudaFuncSetAttribute(kb, cudaFuncAttributeMaxDynamicSharedMemorySize, TCONV_SMEM);
    cudaFuncSetAttribute(ks, cudaFuncAttributeMaxDynamicSharedMemorySize, TCONV_SMEM);

    // layout transforms + precision converts
    zero_stat_kernel<<<3, 256>>>(stat);
    xconv_kernel<<<dim3(N_NODES / 32, 2), dim3(32, 8)>>>(data, x16);
    wconv_kernel<<<(KTAPS * 64 * 128 + 255) / 256, 256>>>(w_a, wa16, 64, KTAPS);
    wconv_kernel<<<(KTAPS * 128 * 128 + 255) / 256, 256>>>(w_b, wb16, 128, KTAPS);
    wconv_kernel<<<(64 * 128 + 255) / 256, 256>>>(w_skip, ws16, 64, 1);

    const int grid = N_NODES / 128;   // 512

    // conv_a (HMMA fp16 1-pass), node-major fp32 out + fused BN_a stats
    ka<<<grid, 256, TCONV_SMEM>>>(x16, wa16, neigh, ya, stat);
    // BN_a finalize + convert c1 to fp16
    stats_fin_kernel<<<1, 128>>>(stat, gamma_a, beta_a, sca, bia);
    yaconv_kernel<<<(N_NODES * COUT / 4) / 256, 256>>>(ya, sca, bia, ya16);
    // conv_b, ch-major out + fused BN_b stats
    kb<<<grid, 256, TCONV_SMEM>>>(ya16, wb16, neigh, yb, stat + 2 * COUT);
    // skip, ch-major out + fused BN_s stats
    ks<<<grid, 256, TCONV_SMEM>>>(x16, ws16, nullptr, sk, stat + 4 * COUT);
    // BN_b + BN_s finalize (no big reads)
    stats_fin2_kernel<<<1, 128>>>(stat + 2 * COUT, gamma_b, beta_b, gamma_s, beta_s, coef);
    // final elementwise
    final_ew_kernel<<<(COUT * N_NODES / 4) / 256, 256>>>(yb, sk, coef, out);
}

// round 16
// speedup vs baseline: 1.3175x; 1.3175x over previous
#include <cuda_runtime.h>
#include <cuda_fp16.h>
#include <cstddef>
#include <cstdint>

#define N_NODES 65536
#define KTAPS   27
#define COUT    128
#define BN_EPS  1e-3f

// ==================== helpers ====================
__device__ __forceinline__ uint32_t smem_to_u32(const void* p) {
    uint32_t a;
    asm("{ .reg .u64 t; cvta.to.shared.u64 t, %1; cvt.u32.u64 %0, t; }" : "=r"(a) : "l"(p));
    return a;
}
__device__ __forceinline__ void ldsm_x4(uint32_t& r0, uint32_t& r1, uint32_t& r2, uint32_t& r3,
                                        uint32_t addr) {
    asm volatile("ldmatrix.sync.aligned.m8n8.x4.shared.b16 {%0,%1,%2,%3}, [%4];"
                 : "=r"(r0), "=r"(r1), "=r"(r2), "=r"(r3) : "r"(addr));
}
__device__ __forceinline__ void mma_f16(float* c, const uint32_t* a, const uint32_t* b) {
    asm volatile(
        "mma.sync.aligned.m16n8k16.row.col.f32.f16.f16.f32 "
        "{%0,%1,%2,%3}, {%4,%5,%6,%7}, {%8,%9}, {%0,%1,%2,%3};"
        : "+f"(c[0]), "+f"(c[1]), "+f"(c[2]), "+f"(c[3])
        : "r"(a[0]), "r"(a[1]), "r"(a[2]), "r"(a[3]), "r"(b[0]), "r"(b[1]));
}
__device__ __forceinline__ void cp16(uint32_t s, const void* g) {
    asm volatile("{ .reg .u64 gg; cvta.to.global.u64 gg, %1;"
                 "  cp.async.cg.shared.global [%0], [gg], 16; }"
                 :: "r"(s), "l"(g) : "memory");
}
#define CP_COMMIT() asm volatile("cp.async.commit_group;" ::: "memory")
#define CP_WAIT1()  asm volatile("cp.async.wait_group 1;" ::: "memory")
#define CP_WAIT0()  asm volatile("cp.async.wait_group 0;" ::: "memory")

// ==================== scratch (static device memory; no allocs) ====================
__device__ __half g_x16[(size_t)N_NODES * 64];            // x fp16, node-major
__device__ __half g_wa16[(size_t)KTAPS * 128 * 64];       // [k][o][c64]
__device__ __half g_wb16[(size_t)KTAPS * 2 * 128 * 64];   // [k][ch][o][c64]
__device__ __half g_ws16[(size_t)128 * 64];
__device__ float  g_ya[(size_t)N_NODES * COUT];           // conv_a out fp32, node-major
__device__ __half g_ya16[(size_t)N_NODES * COUT];         // relu(BN_a(ya)) fp16
__device__ float  g_yb[(size_t)COUT * N_NODES];           // conv_b out, ch-major
__device__ float  g_sk[(size_t)COUT * N_NODES];           // skip out,  ch-major
__device__ float  g_stat[6 * COUT];                       // a:[0,2C) b:[2C,4C) s:[4C,6C)
__device__ float  g_scale_a[COUT];
__device__ float  g_bias_a[COUT];
__device__ float  g_coef[4 * COUT];

// ==================== tiny: zero stat accumulators ====================
__global__ void zero_stat_kernel(float* acc) {
    acc[blockIdx.x * 256 + threadIdx.x] = 0.f;
}

// ==================== x transpose + fp16 convert ====================
__global__ void xconv_kernel(const float* __restrict__ x,
                             __half* __restrict__ x16) {
    __shared__ float tile[32][33];
    int nb = blockIdx.x * 32, cb = blockIdx.y * 32;
    int tx = threadIdx.x, ty = threadIdx.y;
#pragma unroll
    for (int i = 0; i < 4; i++)
        tile[ty + i * 8][tx] = x[(size_t)(cb + ty + i * 8) * N_NODES + nb + tx];
    __syncthreads();
#pragma unroll
    for (int i = 0; i < 4; i++)
        x16[(size_t)(nb + ty + i * 8) * 64 + cb + tx] =
            __float2half_rn(tile[tx][ty + i * 8]);
}

// ==================== weight convert: w[o][c][k] -> fp16 [k][ch64][o][c64] ====================
__global__ void wconv_kernel(const float* __restrict__ w,
                             __half* __restrict__ w16,
                             int C, int K) {
    int i = blockIdx.x * 256 + threadIdx.x;
    int total = 128 * C * K;
    if (i >= total) return;
    int CH = C / 64;
    int cl = i & 63;
    int o  = (i >> 6) & 127;
    int kc = i >> 13;
    int ch = kc % CH;
    int k  = kc / CH;
    int c  = ch * 64 + cl;
    w16[i] = __float2half_rn(w[((size_t)o * C + c) * K + k]);
}

// ==================== gathered conv GEMM on HMMA (fp16, 1-pass, occ 1) ====================
// D[node, out] = sum_{k,c} act[node,k,c] * w[out,k,c]
// 8 warps, warp tile 64x32, CC=64 chunk, 3-stage cp.async ring.
// Epilogue also accumulates per-channel BN partial sums (sum, sumsq) via atomics.
template<int CIN, int KT, bool GATHER, bool CHMAJOR>
__global__ __launch_bounds__(256, 1)
void tconv_kernel(const __half* __restrict__ src,
                  const __half* __restrict__ w16,
                  const int* __restrict__ neigh,
                  float* __restrict__ out,
                  float* __restrict__ statp) {
    constexpr int CH = CIN / 64;
    constexpr int STEPS = KT * CH;
    constexpr int RS = 144;                       // 128 B row + 16 pad
    constexpr uint32_t AH = 0, WH = 18432, BUF = 36864;
    extern __shared__ __align__(16) char smem[];
    const uint32_t sb = smem_to_u32(smem);

    const int t = threadIdx.x;
    const int lane = t & 31, wid = t >> 5;
    const int n_base = blockIdx.x * 128;
    const int warp_m = (wid & 1) * 64;
    const int warp_n = (wid >> 1) * 32;
    const uint32_t aoff_lane = (uint32_t)(warp_m + (lane & 15)) * RS + ((lane & 16) ? 16u : 0u);
    const uint32_t boff_lane = (uint32_t)(warp_n + (lane & 7) + ((lane & 16) ? 8 : 0)) * RS
                               + ((lane & 8) ? 16u : 0u);

    const int row = t >> 1, part = t & 1;

    float acc[4][4][4];
#pragma unroll
    for (int mi = 0; mi < 4; mi++)
#pragma unroll
        for (int ni = 0; ni < 4; ni++)
#pragma unroll
            for (int e = 0; e < 4; e++) acc[mi][ni][e] = 0.f;

    auto j_of = [&](int s) -> int {
        return GATHER ? neigh[(size_t)(n_base + row) * KT + (s / CH)] : (n_base + row);
    };

    auto issue = [&](int s, int j) {
        const uint32_t stg = sb + (uint32_t)(s % 3) * BUF;
        const int k = s / CH, ch = s % CH;
        const __half* ap = src + (size_t)j * CIN + ch * 64 + part * 32;
        const uint32_t ab = stg + AH + (uint32_t)row * RS + part * 64;
#pragma unroll
        for (int i = 0; i < 4; i++)
            cp16(ab + i * 16, ap + i * 8);
        const __half* wp = w16 + ((size_t)(k * CH + ch) << 13) + row * 64 + part * 32;
        const uint32_t wb = stg + WH + (uint32_t)row * RS + part * 64;
#pragma unroll
        for (int i = 0; i < 4; i++)
            cp16(wb + i * 16, wp + i * 8);
        CP_COMMIT();
    };

    int jn = j_of(0);
    issue(0, jn);
    if (STEPS > 1) jn = j_of(1);

    for (int s = 0; s < STEPS; ++s) {
        if (s + 1 < STEPS) {
            issue(s + 1, jn);                    // writes buf (s+1)%3 — safe at depth 3
            if (s + 2 < STEPS) jn = j_of(s + 2);
            CP_WAIT1();
        } else {
            CP_WAIT0();
        }
        __syncthreads();

        const uint32_t sbuf = sb + (uint32_t)(s % 3) * BUF;

#pragma unroll
        for (int k16 = 0; k16 < 4; ++k16) {
            const uint32_t kb = (uint32_t)k16 * 32;
            const uint32_t a_h = sbuf + AH + aoff_lane + kb;
            const uint32_t b_h = sbuf + WH + boff_lane + kb;

            uint32_t ah[4][4], bh[4][2];
#pragma unroll
            for (int mi = 0; mi < 4; mi++)
                ldsm_x4(ah[mi][0], ah[mi][1], ah[mi][2], ah[mi][3], a_h + mi * (16 * RS));
#pragma unroll
            for (int nt = 0; nt < 2; nt++) {
                uint32_t r0, r1, r2, r3;
                ldsm_x4(r0, r1, r2, r3, b_h + nt * (16 * RS));
                bh[2 * nt][0] = r0; bh[2 * nt][1] = r1;
                bh[2 * nt + 1][0] = r2; bh[2 * nt + 1][1] = r3;
            }
#pragma unroll
            for (int mi = 0; mi < 4; mi++)
#pragma unroll
                for (int ni = 0; ni < 4; ni++)
                    mma_f16(acc[mi][ni], ah[mi], bh[ni]);
        }
    }

    // ---- epilogue: store + fused per-channel BN partial stats ----
#pragma unroll
    for (int mi = 0; mi < 4; mi++)
#pragma unroll
        for (int ni = 0; ni < 4; ni++) {
            int r = n_base + warp_m + mi * 16 + (lane >> 2);
            int c = warp_n + ni * 8 + (lane & 3) * 2;
            if (CHMAJOR) {
                out[(size_t)c * N_NODES + r]           = acc[mi][ni][0];
                out[(size_t)(c + 1) * N_NODES + r]     = acc[mi][ni][1];
                out[(size_t)c * N_NODES + r + 8]       = acc[mi][ni][2];
                out[(size_t)(c + 1) * N_NODES + r + 8] = acc[mi][ni][3];
            } else {
                *(float2*)&out[(size_t)r * COUT + c] =
                    make_float2(acc[mi][ni][0], acc[mi][ni][1]);
                *(float2*)&out[(size_t)(r + 8) * COUT + c] =
                    make_float2(acc[mi][ni][2], acc[mi][ni][3]);
            }
        }

    {
        // per-thread channel partials: p = ni*2 + h -> channel warp_n + ni*8 + (lane&3)*2 + h
        float sloc[8], qloc[8];
#pragma unroll
        for (int ni = 0; ni < 4; ni++)
#pragma unroll
            for (int h = 0; h < 2; h++) {
                float s = 0.f, q = 0.f;
#pragma unroll
                for (int mi = 0; mi < 4; mi++) {
                    float v0 = acc[mi][ni][h];
                    float v1 = acc[mi][ni][h + 2];
                    s += v0 + v1;
                    q += v0 * v0 + v1 * v1;
                }
                sloc[ni * 2 + h] = s;
                qloc[ni * 2 + h] = q;
            }
        // reduce over the 8 lanes sharing (lane & 3)
#pragma unroll
        for (int off = 4; off < 32; off <<= 1)
#pragma unroll
            for (int p = 0; p < 8; p++) {
                sloc[p] += __shfl_xor_sync(0xffffffffu, sloc[p], off);
                qloc[p] += __shfl_xor_sync(0xffffffffu, qloc[p], off);
            }
        if ((lane >> 2) == 0) {
#pragma unroll
            for (int p = 0; p < 8; p++) {
                int c = warp_n + (p >> 1) * 8 + (lane & 3) * 2 + (p & 1);
                atomicAdd(&statp[c], sloc[p]);
                atomicAdd(&statp[COUT + c], qloc[p]);
            }
        }
    }
}

// ==================== BN_a finalize ====================
__global__ void stats_fin_kernel(const float* __restrict__ acc,
                                 const float* __restrict__ gamma,
                                 const float* __restrict__ beta,
                                 float* __restrict__ scale,
                                 float* __restrict__ bias) {
    int c = threadIdx.x;
    float mean = acc[c] / N_NODES;
    float var  = acc[COUT + c] / N_NODES - mean * mean;
    float kk   = gamma[c] * rsqrtf(var + BN_EPS);
    scale[c] = kk;
    bias[c]  = beta[c] - kk * mean;
}

// ==================== BN_b + BN_s finalize (from fused accumulators) ====================
__global__ void stats_fin2_kernel(const float* __restrict__ acc,  // [2C,6C) region base
                                  const float* __restrict__ gb,
                                  const float* __restrict__ bb,
                                  const float* __restrict__ gs,
                                  const float* __restrict__ bs,
                                  float* __restrict__ coef) {
    int c = threadIdx.x;
    float m1 = acc[c] / N_NODES;
    float v1 = acc[COUT + c] / N_NODES - m1 * m1;
    float k1 = gb[c] * rsqrtf(v1 + BN_EPS);
    coef[c]            = k1;
    coef[COUT + c]     = bb[c] - k1 * m1;
    float m2 = acc[2 * COUT + c] / N_NODES;
    float v2 = acc[3 * COUT + c] / N_NODES - m2 * m2;
    float k2 = gs[c] * rsqrtf(v2 + BN_EPS);
    coef[2 * COUT + c] = k2;
    coef[3 * COUT + c] = bs[c] - k2 * m2;
}

// ==================== yaconv: relu(BN_a(ya)) -> fp16 ====================
__global__ void yaconv_kernel(const float* __restrict__ ya,
                              const float* __restrict__ scale,
                              const float* __restrict__ bias,
                              __half* __restrict__ y16) {
    int i = blockIdx.x * 256 + threadIdx.x;      // quad index
    int c0 = (i & 31) * 4;
    float4 v  = ((const float4*)ya)[i];
    float4 sc = *(const float4*)(scale + c0);
    float4 bi = *(const float4*)(bias + c0);
    float a0 = fmaxf(fmaf(v.x, sc.x, bi.x), 0.f);
    float a1 = fmaxf(fmaf(v.y, sc.y, bi.y), 0.f);
    float a2 = fmaxf(fmaf(v.z, sc.z, bi.z), 0.f);
    float a3 = fmaxf(fmaf(v.w, sc.w, bi.w), 0.f);
    ((__half2*)y16)[i * 2]     = __floats2half2_rn(a0, a1);
    ((__half2*)y16)[i * 2 + 1] = __floats2half2_rn(a2, a3);
}

// ==================== final: out = relu(BN_b(yb) + BN_s(sk)) ====================
__global__ void final_ew_kernel(const float* __restrict__ yb,
                                const float* __restrict__ sk,
                                const float* __restrict__ coef,
                                float* __restrict__ out) {
    int i = blockIdx.x * 256 + threadIdx.x;
    int o = i >> 14;
    float sb = coef[o],            bb = coef[COUT + o];
    float ss = coef[2 * COUT + o], bs = coef[3 * COUT + o];
    float4 a = ((const float4*)yb)[i];
    float4 b = ((const float4*)sk)[i];
    float4 r;
    r.x = fmaxf(fmaf(sb, a.x, bb) + fmaf(ss, b.x, bs), 0.f);
    r.y = fmaxf(fmaf(sb, a.y, bb) + fmaf(ss, b.y, bs), 0.f);
    r.z = fmaxf(fmaf(sb, a.z, bb) + fmaf(ss, b.z, bs), 0.f);
    r.w = fmaxf(fmaf(sb, a.w, bb) + fmaf(ss, b.w, bs), 0.f);
    ((float4*)out)[i] = r;
}

// ==================== host ====================
static constexpr int TCONV_SMEM = 3 * 36864;   // 110592 B

extern "C" void kernel_launch(void* const* d_in, const int* in_sizes, int n_in,
                              void* d_out, int out_size) {
    const float* data    = (const float*)d_in[0];
    const int*   neigh   = (const int*)  d_in[1];
    const float* w_a     = (const float*)d_in[2];
    const float* w_b     = (const float*)d_in[3];
    const float* w_skip  = (const float*)d_in[4];
    const float* gamma_a = (const float*)d_in[5];
    const float* beta_a  = (const float*)d_in[6];
    const float* gamma_b = (const float*)d_in[7];
    const float* beta_b  = (const float*)d_in[8];
    const float* gamma_s = (const float*)d_in[9];
    const float* beta_s  = (const float*)d_in[10];
    float* out = (float*)d_out;

    __half *x16, *wa16, *wb16, *ws16, *ya16;
    float *ya, *yb, *sk, *stat, *sca, *bia, *coef;
    cudaGetSymbolAddress((void**)&x16,  g_x16);
    cudaGetSymbolAddress((void**)&wa16, g_wa16);
    cudaGetSymbolAddress((void**)&wb16, g_wb16);
    cudaGetSymbolAddress((void**)&ws16, g_ws16);
    cudaGetSymbolAddress((void**)&ya,   g_ya);
    cudaGetSymbolAddress((void**)&ya16, g_ya16);
    cudaGetSymbolAddress((void**)&yb,   g_yb);
    cudaGetSymbolAddress((void**)&sk,   g_sk);
    cudaGetSymbolAddress((void**)&stat, g_stat);
    cudaGetSymbolAddress((void**)&sca,  g_scale_a);
    cudaGetSymbolAddress((void**)&bia,  g_bias_a);
    cudaGetSymbolAddress((void**)&coef, g_coef);

    auto* ka = tconv_kernel<64, KTAPS, true, false>;
    auto* kb = tconv_kernel<128, KTAPS, true, true>;
    auto* ks = tconv_kernel<64, 1, false, true>;
    cudaFuncSetAttribute(ka, cudaFuncAttributeMaxDynamicSharedMemorySize, TCONV_SMEM);
    cudaFuncSetAttribute(kb, cudaFuncAttributeMaxDynamicSharedMemorySize, TCONV_SMEM);
    cudaFuncSetAttribute(ks, cudaFuncAttributeMaxDynamicSharedMemorySize, TCONV_SMEM);

    // layout transforms + precision converts
    zero_stat_kernel<<<3, 256>>>(stat);
    xconv_kernel<<<dim3(N_NODES / 32, 2), dim3(32, 8)>>>(data, x16);
    wconv_kernel<<<(KTAPS * 64 * 128 + 255) / 256, 256>>>(w_a, wa16, 64, KTAPS);
    wconv_kernel<<<(KTAPS * 128 * 128 + 255) / 256, 256>>>(w_b, wb16, 128, KTAPS);
    wconv_kernel<<<(64 * 128 + 255) / 256, 256>>>(w_skip, ws16, 64, 1);

    const int grid = N_NODES / 128;   // 512

    // conv_a (HMMA fp16 1-pass), node-major fp32 out + fused BN_a stats
    ka<<<grid, 256, TCONV_SMEM>>>(x16, wa16, neigh, ya, stat);
    // BN_a finalize + convert c1 to fp16
    stats_fin_kernel<<<1, 128>>>(stat, gamma_a, beta_a, sca, bia);
    yaconv_kernel<<<(N_NODES * COUT / 4) / 256, 256>>>(ya, sca, bia, ya16);
    // conv_b, ch-major out + fused BN_b stats
    kb<<<grid, 256, TCONV_SMEM>>>(ya16, wb16, neigh, yb, stat + 2 * COUT);
    // skip, ch-major out + fused BN_s stats
    ks<<<grid, 256, TCONV_SMEM>>>(x16, ws16, nullptr, sk, stat + 4 * COUT);
    // BN_b + BN_s finalize (no big reads)
    stats_fin2_kernel<<<1, 128>>>(stat + 2 * COUT, gamma_b, beta_b, gamma_s, beta_s, coef);
    // final elementwise
    final_ew_kernel<<<(COUT * N_NODES / 4) / 256, 256>>>(yb, sk, coef, out);
}